// round 15
// baseline (speedup 1.0000x reference)
#include <cuda_runtime.h>
#include <math.h>
#include <stdint.h>

#define NN 100000
#define EE 500000
#define GG 2048
#define DIM 128
#define OUTD 64
#define BN_EPS 1e-5f

// ---------------- scratch (device globals; no allocation allowed) ----------------
__device__ float g_agg[NN * DIM];
__device__ float g_y[NN * DIM];
__device__ float g_h[NN * DIM];
__device__ float g_pool[GG * DIM];
__device__ float g_code[GG * OUTD];
__device__ float g_colsum1[DIM];
__device__ float g_colsumsq1[DIM];
__device__ float g_colsum2[DIM];
__device__ float g_colsumsq2[DIM];
__device__ int g_src[EE];
__device__ int g_dst[EE];
__device__ int g_batch[NN];
__device__ int g_deg[NN];
__device__ int g_off[NN + 1];
__device__ int g_cursor[NN];
__device__ int g_sorted_src[EE];
__device__ int g_sorted_dst[EE];

// ---------------- helpers ----------------
__device__ __forceinline__ void ffma2(unsigned long long& d, unsigned long long a,
                                      unsigned long long b) {
    asm("fma.rn.f32x2 %0, %1, %2, %0;" : "+l"(d) : "l"(a), "l"(b));
}
__device__ __forceinline__ float2 unpack2(unsigned long long v) {
    float2 r;
    asm("mov.b64 {%0, %1}, %2;" : "=f"(r.x), "=f"(r.y) : "l"(v));
    return r;
}
__device__ __forceinline__ void red_add_v4(float* p, float a, float b, float c, float d) {
    asm volatile("red.global.add.v4.f32 [%0], {%1, %2, %3, %4};"
                 :: "l"(p), "f"(a), "f"(b), "f"(c), "f"(d) : "memory");
}
__device__ __forceinline__ bool is_int64_layout(const int* raw, int n_vals) {
    int nchk = n_vals < 64 ? n_vals : 64;
    for (int i = 0; i < nchk; i++)
        if (raw[2 * i + 1] != 0) return false;
    return true;
}

// ---------------- kernel 0: batch convert + zero deg/pool/stats/agg ----------------
__global__ void zero_misc(const int* __restrict__ raw, int* __restrict__ batch,
                          int* __restrict__ deg, float* __restrict__ pool,
                          float* __restrict__ cs1, float* __restrict__ cq1,
                          float* __restrict__ cs2, float* __restrict__ cq2,
                          float* __restrict__ agg) {
    bool w = is_int64_layout(raw, NN);
    int i = blockIdx.x * blockDim.x + threadIdx.x;
    int stride = gridDim.x * blockDim.x;
    if (w) {
        const long long* r = (const long long*)raw;
        for (int n = i; n < NN; n += stride) batch[n] = (int)r[n];
    } else {
        for (int n = i; n < NN; n += stride) batch[n] = raw[n];
    }
    for (int n = i; n < NN; n += stride) deg[n] = 0;
    if (i < GG * DIM / 4) ((float4*)pool)[i] = make_float4(0.f, 0.f, 0.f, 0.f);
    if (i < DIM) { cs1[i] = 0.f; cq1[i] = 0.f; cs2[i] = 0.f; cq2[i] = 0.f; }
    float4* a4 = (float4*)agg;
    int n4 = NN * DIM / 4;
    for (int k = i; k < n4; k += stride) a4[k] = make_float4(0.f, 0.f, 0.f, 0.f);
}

// ---------------- kernel 1: edge convert + in-degree histogram (by DST) ------------
__global__ void convert_edges_hist(const int* __restrict__ raw, int* __restrict__ src,
                                   int* __restrict__ dst, int* __restrict__ deg) {
    bool w = is_int64_layout(raw, 2 * EE);
    int i = blockIdx.x * blockDim.x + threadIdx.x;
    int stride = gridDim.x * blockDim.x;
    if (w) {
        const long long* r = (const long long*)raw;
        for (int e = i; e < EE; e += stride) {
            int s = (int)r[e];
            int d = (int)r[EE + e];
            src[e] = s;
            dst[e] = d;
            if ((unsigned)s < NN && (unsigned)d < NN) atomicAdd(&deg[d], 1);
        }
    } else {
        for (int e = i; e < EE; e += stride) {
            int s = raw[e];
            int d = raw[EE + e];
            src[e] = s;
            dst[e] = d;
            if ((unsigned)s < NN && (unsigned)d < NN) atomicAdd(&deg[d], 1);
        }
    }
}

// ---------------- kernel 2: single-block exclusive scan ----------------
#define SCAN_THREADS 1024
#define SCAN_CHUNK ((NN + SCAN_THREADS - 1) / SCAN_THREADS)   // 98
__global__ void scan_csr(const int* __restrict__ deg, int* __restrict__ off,
                         int* __restrict__ cursor) {
    __shared__ int sc[SCAN_THREADS];
    int t = threadIdx.x;
    int begin = t * SCAN_CHUNK;
    int end = min(begin + SCAN_CHUNK, NN);
    int lsum = 0;
    for (int i = begin; i < end; i++) lsum += deg[i];
    sc[t] = lsum;
    __syncthreads();
    for (int o = 1; o < SCAN_THREADS; o <<= 1) {
        int v = (t >= o) ? sc[t - o] : 0;
        __syncthreads();
        sc[t] += v;
        __syncthreads();
    }
    int run = sc[t] - lsum;
    for (int i = begin; i < end; i++) {
        off[i] = run;
        cursor[i] = run;
        run += deg[i];
    }
    if (t == SCAN_THREADS - 1) off[NN] = sc[SCAN_THREADS - 1];
}

// ---------------- kernel 3: scatter edges sorted by dst ----------------
__global__ void scatter_csr(const int* __restrict__ src, const int* __restrict__ dst,
                            int* __restrict__ cursor, int* __restrict__ sorted_src,
                            int* __restrict__ sorted_dst) {
    int i = blockIdx.x * blockDim.x + threadIdx.x;
    int stride = gridDim.x * blockDim.x;
    for (int e = i; e < EE; e += stride) {
        int s = src[e];
        int d = dst[e];
        if ((unsigned)s < NN && (unsigned)d < NN) {
            int p = atomicAdd(&cursor[d], 1);
            sorted_src[p] = s;
            sorted_dst[p] = d;
        }
    }
}

// ---------------- edge aggregation (flat, dst-sorted order, red.v4) ----------------
__global__ void edge_agg(const float* __restrict__ h, const int* __restrict__ src,
                         const int* __restrict__ dst, float* __restrict__ agg, int E) {
    int t = blockIdx.x * blockDim.x + threadIdx.x;
    int e = t >> 5;
    int lane = t & 31;
    if (e >= E) return;
    int s = src[e];
    int d = dst[e];
    if ((unsigned)s >= NN || (unsigned)d >= NN) return;
    float4 v = ((const float4*)(h + (size_t)s * DIM))[lane];
    red_add_v4(agg + (size_t)d * DIM + lane * 4, v.x, v.y, v.z, v.w);
}

// ---------------- pooling ----------------
__global__ void pool_kernel(const float* __restrict__ h, const int* __restrict__ batch,
                            float* __restrict__ pool, int n_nodes) {
    int t = blockIdx.x * blockDim.x + threadIdx.x;
    int n = t >> 5;
    int lane = t & 31;
    if (n >= n_nodes) return;
    int g = batch[n];
    if ((unsigned)g >= GG) return;
    float4 v = ((const float4*)(h + (size_t)n * DIM))[lane];
    red_add_v4(pool + (size_t)g * DIM + lane * 4, v.x, v.y, v.z, v.w);
}

// ---------------- FFMA2 GEMM (R7 mainloop; fused BN-finalize prologue + agg-zero) ----
// IN_MODE 1: A' = A0 + A1 ; 2: A' = relu(scale*A0 + shift) with scale/shift computed
// in-CTA from colsum/colsumsq/gamma/beta. STATS: fused column stats of pre-act output.
// ZEROA: epilogue zeros this CTA's 64-row slice of aggz.
#define WT_STRIDE 132
#define OFF_WT 0
#define OFF_A (128 * WT_STRIDE * 4)                  // 67584
#define GEMM_SMEM (OFF_A + 64 * 128 * 4)             // 100352

template <int IN_MODE, bool OUT_RELU, bool STATS, bool ZEROA>
__global__ __launch_bounds__(256, 2) void gemm128(
    const float* __restrict__ A0, const float* __restrict__ A1,
    const float* __restrict__ csum_in, const float* __restrict__ csq_in,
    const float* __restrict__ gamma, const float* __restrict__ beta,
    const float* __restrict__ W, const float* __restrict__ bias,
    float* __restrict__ C, int M,
    float* __restrict__ colsum, float* __restrict__ colsumsq,
    float* __restrict__ aggz) {
    extern __shared__ float sm[];
    float* Wt = sm + OFF_WT / 4;
    float* Asm = sm + OFF_A / 4;
    __shared__ float sbias[128];
    __shared__ float scs[128], scq[128];
    __shared__ float sscale[128], sshift[128];
    int tid = threadIdx.x;
    int row0 = blockIdx.x * 64;

    if (IN_MODE == 2) {
        if (tid < 128) {
            float invM = 1.f / (float)M;
            float mean = csum_in[tid] * invM;
            float var = csq_in[tid] * invM - mean * mean;
            float sc = gamma[tid] * rsqrtf(var + BN_EPS);
            sscale[tid] = sc;
            sshift[tid] = beta[tid] - mean * sc;
        }
        __syncthreads();
    }

    // stage W transposed: 4x4 blocks through registers
    {
        const float4* Wv = (const float4*)W;
#pragma unroll
        for (int i = 0; i < 4; i++) {
            int idx = tid + i * 256;      // 1024 blocks
            int kb = idx >> 5, cb = idx & 31;
            int k0 = kb * 4, c0 = cb * 4;
            float4 r0 = Wv[(k0 + 0) * 32 + cb];
            float4 r1 = Wv[(k0 + 1) * 32 + cb];
            float4 r2 = Wv[(k0 + 2) * 32 + cb];
            float4 r3 = Wv[(k0 + 3) * 32 + cb];
            *(float4*)(Wt + (c0 + 0) * WT_STRIDE + k0) = make_float4(r0.x, r1.x, r2.x, r3.x);
            *(float4*)(Wt + (c0 + 1) * WT_STRIDE + k0) = make_float4(r0.y, r1.y, r2.y, r3.y);
            *(float4*)(Wt + (c0 + 2) * WT_STRIDE + k0) = make_float4(r0.z, r1.z, r2.z, r3.z);
            *(float4*)(Wt + (c0 + 3) * WT_STRIDE + k0) = make_float4(r0.w, r1.w, r2.w, r3.w);
        }
    }
    if (tid < 128) {
        sbias[tid] = bias[tid];
        if (STATS) { scs[tid] = 0.f; scq[tid] = 0.f; }
    }
    // stage A tile with input transform
    {
        float4* Asv = (float4*)Asm;
#pragma unroll
        for (int i = 0; i < 8; i++) {
            int idx = tid + i * 256;
            int r = idx >> 5;
            int c4 = idx & 31;
            int gr = row0 + r;
            float4 v = make_float4(0.f, 0.f, 0.f, 0.f);
            if (gr < M) {
                v = ((const float4*)A0)[(size_t)gr * 32 + c4];
                if (IN_MODE == 1) {
                    float4 u = ((const float4*)A1)[(size_t)gr * 32 + c4];
                    v.x += u.x; v.y += u.y; v.z += u.z; v.w += u.w;
                } else if (IN_MODE == 2) {
                    int col = c4 * 4;
                    v.x = fmaxf(v.x * sscale[col + 0] + sshift[col + 0], 0.f);
                    v.y = fmaxf(v.y * sscale[col + 1] + sshift[col + 1], 0.f);
                    v.z = fmaxf(v.z * sscale[col + 2] + sshift[col + 2], 0.f);
                    v.w = fmaxf(v.w * sscale[col + 3] + sshift[col + 3], 0.f);
                }
            }
            Asv[idx] = v;
        }
    }
    __syncthreads();

    int rid = tid >> 5;  // warp -> rows rid*8..+7
    int cid = tid & 31;  // lane -> cols cid + {0,32,64,96}
    unsigned long long acc[8][4];
#pragma unroll
    for (int i = 0; i < 8; i++)
#pragma unroll
        for (int c = 0; c < 4; c++) acc[i][c] = 0ull;

    const float4* Asv = (const float4*)Asm;
#pragma unroll
    for (int k4 = 0; k4 < 32; k4++) {
        unsigned long long a2[8][2];
#pragma unroll
        for (int i = 0; i < 8; i++) {
            float4 av = Asv[(rid * 8 + i) * 32 + k4];  // warp-broadcast
            a2[i][0] = *(unsigned long long*)&av.x;
            a2[i][1] = *(unsigned long long*)&av.z;
        }
#pragma unroll
        for (int c = 0; c < 4; c++) {
            float4 wv = *(const float4*)(Wt + (cid + 32 * c) * WT_STRIDE + k4 * 4);
            unsigned long long w0 = *(unsigned long long*)&wv.x;
            unsigned long long w1 = *(unsigned long long*)&wv.z;
#pragma unroll
            for (int i = 0; i < 8; i++) {
                ffma2(acc[i][c], a2[i][0], w0);
                ffma2(acc[i][c], a2[i][1], w1);
            }
        }
    }

    // epilogue
    float cs[4] = {0.f, 0.f, 0.f, 0.f};
    float cq[4] = {0.f, 0.f, 0.f, 0.f};
#pragma unroll
    for (int i = 0; i < 8; i++) {
        int gr = row0 + rid * 8 + i;
        if (gr < M) {
#pragma unroll
            for (int c = 0; c < 4; c++) {
                int col = cid + 32 * c;
                float2 p = unpack2(acc[i][c]);
                float y = p.x + p.y + sbias[col];
                if (STATS) { cs[c] += y; cq[c] += y * y; }
                C[(size_t)gr * 128 + col] = OUT_RELU ? fmaxf(y, 0.f) : y;
            }
            if (ZEROA)
                ((float4*)aggz)[(size_t)gr * 32 + cid] = make_float4(0.f, 0.f, 0.f, 0.f);
        }
    }
    if (STATS) {
#pragma unroll
        for (int c = 0; c < 4; c++) {
            atomicAdd(&scs[cid + 32 * c], cs[c]);
            atomicAdd(&scq[cid + 32 * c], cq[c]);
        }
        __syncthreads();
        if (tid < 128) {
            atomicAdd(&colsum[tid], scs[tid]);
            atomicAdd(&colsumsq[tid], scq[tid]);
        }
    }
}

// ---------------- code MLP branch ----------------
__global__ void code_mlp(const float* __restrict__ code_x,
                         const float* __restrict__ w1, const float* __restrict__ b1,
                         const float* __restrict__ w2, const float* __restrict__ b2,
                         const float* __restrict__ w3, const float* __restrict__ b3,
                         float* __restrict__ code_out) {
    __shared__ float buf0[128], buf1[128];
    __shared__ float red[64];
    __shared__ float s_mx, s_lse;
    int g = blockIdx.x, j = threadIdx.x;
    buf0[j] = code_x[(size_t)g * 128 + j];
    __syncthreads();
    float acc = b1[j];
    for (int k = 0; k < 128; k++) acc += buf0[k] * w1[k * 128 + j];
    buf1[j] = fmaxf(acc, 0.f);
    __syncthreads();
    float acc2 = b2[j];
    for (int k = 0; k < 128; k++) acc2 += buf1[k] * w2[k * 128 + j];
    buf0[j] = fmaxf(acc2, 0.f);
    __syncthreads();
    float v = 0.f;
    if (j < 64) {
        v = b3[j];
        for (int k = 0; k < 128; k++) v += buf0[k] * w3[k * 64 + j];
        red[j] = v;
    }
    __syncthreads();
    if (j == 0) {
        float m = red[0];
        for (int i = 1; i < 64; i++) m = fmaxf(m, red[i]);
        float s = 0.f;
        for (int i = 0; i < 64; i++) s += expf(red[i] - m);
        s_mx = m;
        s_lse = logf(s);
    }
    __syncthreads();
    if (j < 64) code_out[(size_t)g * 64 + j] = v - s_mx - s_lse;
}

// ---------------- head ----------------
__global__ void head_kernel(const float* __restrict__ pool,
                            const float* __restrict__ l1w, const float* __restrict__ l1b,
                            const float* __restrict__ l2w, const float* __restrict__ l2b,
                            const float* __restrict__ code,
                            const float* __restrict__ finw, const float* __restrict__ finb,
                            float* __restrict__ out) {
    __shared__ float p[128], t[128], cc[128];
    __shared__ float r0[128], r1[128];
    int g = blockIdx.x, j = threadIdx.x;
    p[j] = pool[(size_t)g * 128 + j];
    __syncthreads();
    float a = l1b[j];
    for (int k = 0; k < 128; k++) a += p[k] * l1w[k * 128 + j];
    t[j] = fmaxf(a, 0.f);
    __syncthreads();
    if (j < 64) {
        float v = l2b[j];
        for (int k = 0; k < 128; k++) v += t[k] * l2w[k * 64 + j];
        cc[64 + j] = v;
        cc[j] = code[(size_t)g * 64 + j];
    }
    __syncthreads();
    r0[j] = cc[j] * finw[j * 2 + 0];
    r1[j] = cc[j] * finw[j * 2 + 1];
    __syncthreads();
    if (j == 0) {
        float o0 = finb[0], o1 = finb[1];
        for (int k = 0; k < 128; k++) { o0 += r0[k]; o1 += r1[k]; }
        float m = fmaxf(o0, o1);
        float l = m + logf(expf(o0 - m) + expf(o1 - m));
        out[(size_t)g * 2 + 0] = o0 - l;
        out[(size_t)g * 2 + 1] = o1 - l;
    }
}

// ---------------- launcher ----------------
extern "C" void kernel_launch(void* const* d_in, const int* in_sizes, int n_in,
                              void* d_out, int out_size) {
    const float* x = (const float*)d_in[0];
    const int* ei_raw = (const int*)d_in[1];
    const int* batch_raw = (const int*)d_in[2];
    const float* code_x = (const float*)d_in[3];
    const float* c1_w1 = (const float*)d_in[4];
    const float* c1_b1 = (const float*)d_in[5];
    const float* c1_g = (const float*)d_in[6];
    const float* c1_be = (const float*)d_in[7];
    const float* c1_w2 = (const float*)d_in[8];
    const float* c1_b2 = (const float*)d_in[9];
    const float* c2_w1 = (const float*)d_in[10];
    const float* c2_b1 = (const float*)d_in[11];
    const float* c2_g = (const float*)d_in[12];
    const float* c2_be = (const float*)d_in[13];
    const float* c2_w2 = (const float*)d_in[14];
    const float* c2_b2 = (const float*)d_in[15];
    const float* gl1_w = (const float*)d_in[16];
    const float* gl1_b = (const float*)d_in[17];
    const float* gl2_w = (const float*)d_in[18];
    const float* gl2_b = (const float*)d_in[19];
    const float* fc1_w = (const float*)d_in[20];
    const float* fc1_b = (const float*)d_in[21];
    const float* fc2_w = (const float*)d_in[22];
    const float* fc2_b = (const float*)d_in[23];
    const float* fc3_w = (const float*)d_in[24];
    const float* fc3_b = (const float*)d_in[25];
    const float* fin_w = (const float*)d_in[26];
    const float* fin_b = (const float*)d_in[27];
    float* out = (float*)d_out;

    float *agg, *y, *h, *pool, *code, *cs1, *cq1, *cs2, *cq2;
    int *srcp, *dstp, *batchp, *deg, *off, *cursor, *ssrc, *sdst;
    cudaGetSymbolAddress((void**)&agg, g_agg);
    cudaGetSymbolAddress((void**)&y, g_y);
    cudaGetSymbolAddress((void**)&h, g_h);
    cudaGetSymbolAddress((void**)&pool, g_pool);
    cudaGetSymbolAddress((void**)&code, g_code);
    cudaGetSymbolAddress((void**)&cs1, g_colsum1);
    cudaGetSymbolAddress((void**)&cq1, g_colsumsq1);
    cudaGetSymbolAddress((void**)&cs2, g_colsum2);
    cudaGetSymbolAddress((void**)&cq2, g_colsumsq2);
    cudaGetSymbolAddress((void**)&srcp, g_src);
    cudaGetSymbolAddress((void**)&dstp, g_dst);
    cudaGetSymbolAddress((void**)&batchp, g_batch);
    cudaGetSymbolAddress((void**)&deg, g_deg);
    cudaGetSymbolAddress((void**)&off, g_off);
    cudaGetSymbolAddress((void**)&cursor, g_cursor);
    cudaGetSymbolAddress((void**)&ssrc, g_sorted_src);
    cudaGetSymbolAddress((void**)&sdst, g_sorted_dst);

    cudaFuncSetAttribute(gemm128<1, false, true, false>, cudaFuncAttributeMaxDynamicSharedMemorySize, GEMM_SMEM);
    cudaFuncSetAttribute(gemm128<2, true, false, true>, cudaFuncAttributeMaxDynamicSharedMemorySize, GEMM_SMEM);
    cudaFuncSetAttribute(gemm128<2, true, false, false>, cudaFuncAttributeMaxDynamicSharedMemorySize, GEMM_SMEM);

    const int gemm_blocks = (NN + 63) / 64;           // 1563
    const int edge_blocks = (EE * 32 + 255) / 256;    // 62500

    // ---- CSR-style dst-sort of edges (shared by both convs) ----
    zero_misc<<<512, 256>>>(batch_raw, batchp, deg, pool, cs1, cq1, cs2, cq2, agg);   // 0
    convert_edges_hist<<<512, 256>>>(ei_raw, srcp, dstp, deg);                        // 1
    scan_csr<<<1, SCAN_THREADS>>>(deg, off, cursor);                                  // 2
    scatter_csr<<<512, 256>>>(srcp, dstp, cursor, ssrc, sdst);                        // 3

    // ---- conv1 ----
    edge_agg<<<edge_blocks, 256>>>(x, ssrc, sdst, agg, EE);                           // 4
    gemm128<1, false, true, false><<<gemm_blocks, 256, GEMM_SMEM>>>(                  // 5 (profiled)
        x, agg, nullptr, nullptr, nullptr, nullptr, c1_w1, c1_b1, y, NN, cs1, cq1, nullptr);
    code_mlp<<<GG, 128>>>(code_x, fc1_w, fc1_b, fc2_w, fc2_b, fc3_w, fc3_b, code);
    // gemm2: fused BN-finalize(cs1) + relu, zeroes agg for conv2 in epilogue
    gemm128<2, true, false, true><<<gemm_blocks, 256, GEMM_SMEM>>>(
        y, nullptr, cs1, cq1, c1_g, c1_be, c1_w2, c1_b2, h, NN, nullptr, nullptr, agg);

    // ---- conv2 ----
    edge_agg<<<edge_blocks, 256>>>(h, ssrc, sdst, agg, EE);
    gemm128<1, false, true, false><<<gemm_blocks, 256, GEMM_SMEM>>>(
        h, agg, nullptr, nullptr, nullptr, nullptr, c2_w1, c2_b1, y, NN, cs2, cq2, nullptr);
    gemm128<2, true, false, false><<<gemm_blocks, 256, GEMM_SMEM>>>(
        y, nullptr, cs2, cq2, c2_g, c2_be, c2_w2, c2_b2, h, NN, nullptr, nullptr, nullptr);

    // ---- pool + head ----
    pool_kernel<<<(NN * 32 + 255) / 256, 256>>>(h, batchp, pool, NN);
    head_kernel<<<GG, 128>>>(pool, gl1_w, gl1_b, gl2_w, gl2_b, code, fin_w, fin_b, out);
}

// round 16
// speedup vs baseline: 1.2895x; 1.2895x over previous
#include <cuda_runtime.h>
#include <math.h>
#include <stdint.h>

#define NN 100000
#define EE 500000
#define GG 2048
#define DIM 128
#define OUTD 64
#define BN_EPS 1e-5f

// ---------------- scratch (device globals; no allocation allowed) ----------------
__device__ float g_agg[NN * DIM];
__device__ float g_y[NN * DIM];
__device__ float g_h[NN * DIM];
__device__ float g_pool[GG * DIM];
__device__ float g_code[GG * OUTD];
__device__ float g_colsum1[DIM];
__device__ float g_colsumsq1[DIM];
__device__ float g_colsum2[DIM];
__device__ float g_colsumsq2[DIM];
__device__ int g_src[EE];
__device__ int g_dst[EE];
__device__ int g_batch[NN];

// ---------------- helpers ----------------
__device__ __forceinline__ void ffma2(unsigned long long& d, unsigned long long a,
                                      unsigned long long b) {
    asm("fma.rn.f32x2 %0, %1, %2, %0;" : "+l"(d) : "l"(a), "l"(b));
}
__device__ __forceinline__ float2 unpack2(unsigned long long v) {
    float2 r;
    asm("mov.b64 {%0, %1}, %2;" : "=f"(r.x), "=f"(r.y) : "l"(v));
    return r;
}
__device__ __forceinline__ void red_add_v4(float* p, float a, float b, float c, float d) {
    asm volatile("red.global.add.v4.f32 [%0], {%1, %2, %3, %4};"
                 :: "l"(p), "f"(a), "f"(b), "f"(c), "f"(d) : "memory");
}
__device__ __forceinline__ bool is_int64_layout(const int* raw, int n_vals) {
    int nchk = n_vals < 64 ? n_vals : 64;
    for (int i = 0; i < nchk; i++)
        if (raw[2 * i + 1] != 0) return false;
    return true;
}

// ---------------- index canonicalization + agg zeroing (R13, unsorted) ----------------
__global__ void convert_edges_zero(const int* __restrict__ raw, int* __restrict__ src,
                                   int* __restrict__ dst, float* __restrict__ agg) {
    bool w = is_int64_layout(raw, 2 * EE);
    int i = blockIdx.x * blockDim.x + threadIdx.x;
    int stride = gridDim.x * blockDim.x;
    if (w) {
        const long long* r = (const long long*)raw;
        for (int e = i; e < EE; e += stride) {
            src[e] = (int)r[e];
            dst[e] = (int)r[EE + e];
        }
    } else {
        for (int e = i; e < EE; e += stride) {
            src[e] = raw[e];
            dst[e] = raw[EE + e];
        }
    }
    float4* a4 = (float4*)agg;
    int n4 = NN * DIM / 4;
    for (int k = i; k < n4; k += stride) a4[k] = make_float4(0.f, 0.f, 0.f, 0.f);
}

__global__ void convert_batch(const int* __restrict__ raw, int* __restrict__ out,
                              float* __restrict__ pool,
                              float* __restrict__ cs1, float* __restrict__ cq1,
                              float* __restrict__ cs2, float* __restrict__ cq2) {
    bool w = is_int64_layout(raw, NN);
    int i = blockIdx.x * blockDim.x + threadIdx.x;
    int stride = gridDim.x * blockDim.x;
    if (w) {
        const long long* r = (const long long*)raw;
        for (int n = i; n < NN; n += stride) out[n] = (int)r[n];
    } else {
        for (int n = i; n < NN; n += stride) out[n] = raw[n];
    }
    if (i < GG * DIM / 4) ((float4*)pool)[i] = make_float4(0.f, 0.f, 0.f, 0.f);
    if (i < DIM) { cs1[i] = 0.f; cq1[i] = 0.f; cs2[i] = 0.f; cq2[i] = 0.f; }
}

// ---------------- edge aggregation (32 lanes/edge, red.v4, natural order) ------------
__global__ void edge_agg(const float* __restrict__ h, const int* __restrict__ src,
                         const int* __restrict__ dst, float* __restrict__ agg, int E) {
    int t = blockIdx.x * blockDim.x + threadIdx.x;
    int e = t >> 5;
    int lane = t & 31;
    if (e >= E) return;
    int s = src[e];
    int d = dst[e];
    if ((unsigned)s >= NN || (unsigned)d >= NN) return;
    float4 v = ((const float4*)(h + (size_t)s * DIM))[lane];
    red_add_v4(agg + (size_t)d * DIM + lane * 4, v.x, v.y, v.z, v.w);
}

// ---------------- pooling ----------------
__global__ void pool_kernel(const float* __restrict__ h, const int* __restrict__ batch,
                            float* __restrict__ pool, int n_nodes) {
    int t = blockIdx.x * blockDim.x + threadIdx.x;
    int n = t >> 5;
    int lane = t & 31;
    if (n >= n_nodes) return;
    int g = batch[n];
    if ((unsigned)g >= GG) return;
    float4 v = ((const float4*)(h + (size_t)n * DIM))[lane];
    red_add_v4(pool + (size_t)g * DIM + lane * 4, v.x, v.y, v.z, v.w);
}

// ---------------- FFMA2 GEMM (R7 mainloop; fused BN-finalize prologue + agg-zero) ----
// IN_MODE 1: A' = A0 + A1 ; 2: A' = relu(scale*A0 + shift), scale/shift computed
// in-CTA from colsum/colsumsq/gamma/beta. STATS: fused column stats of pre-act output.
// ZEROA: epilogue zeros this CTA's 64-row slice of aggz.
#define WT_STRIDE 132
#define OFF_WT 0
#define OFF_A (128 * WT_STRIDE * 4)                  // 67584
#define GEMM_SMEM (OFF_A + 64 * 128 * 4)             // 100352

template <int IN_MODE, bool OUT_RELU, bool STATS, bool ZEROA>
__global__ __launch_bounds__(256, 2) void gemm128(
    const float* __restrict__ A0, const float* __restrict__ A1,
    const float* __restrict__ csum_in, const float* __restrict__ csq_in,
    const float* __restrict__ gamma, const float* __restrict__ beta,
    const float* __restrict__ W, const float* __restrict__ bias,
    float* __restrict__ C, int M,
    float* __restrict__ colsum, float* __restrict__ colsumsq,
    float* __restrict__ aggz) {
    extern __shared__ float sm[];
    float* Wt = sm + OFF_WT / 4;
    float* Asm = sm + OFF_A / 4;
    __shared__ float sbias[128];
    __shared__ float scs[128], scq[128];
    __shared__ float sscale[128], sshift[128];
    int tid = threadIdx.x;
    int row0 = blockIdx.x * 64;

    if (IN_MODE == 2) {
        if (tid < 128) {
            float invM = 1.f / (float)M;
            float mean = csum_in[tid] * invM;
            float var = csq_in[tid] * invM - mean * mean;
            float sc = gamma[tid] * rsqrtf(var + BN_EPS);
            sscale[tid] = sc;
            sshift[tid] = beta[tid] - mean * sc;
        }
        __syncthreads();
    }

    // stage W transposed: 4x4 blocks through registers
    {
        const float4* Wv = (const float4*)W;
#pragma unroll
        for (int i = 0; i < 4; i++) {
            int idx = tid + i * 256;      // 1024 blocks
            int kb = idx >> 5, cb = idx & 31;
            int k0 = kb * 4, c0 = cb * 4;
            float4 r0 = Wv[(k0 + 0) * 32 + cb];
            float4 r1 = Wv[(k0 + 1) * 32 + cb];
            float4 r2 = Wv[(k0 + 2) * 32 + cb];
            float4 r3 = Wv[(k0 + 3) * 32 + cb];
            *(float4*)(Wt + (c0 + 0) * WT_STRIDE + k0) = make_float4(r0.x, r1.x, r2.x, r3.x);
            *(float4*)(Wt + (c0 + 1) * WT_STRIDE + k0) = make_float4(r0.y, r1.y, r2.y, r3.y);
            *(float4*)(Wt + (c0 + 2) * WT_STRIDE + k0) = make_float4(r0.z, r1.z, r2.z, r3.z);
            *(float4*)(Wt + (c0 + 3) * WT_STRIDE + k0) = make_float4(r0.w, r1.w, r2.w, r3.w);
        }
    }
    if (tid < 128) {
        sbias[tid] = bias[tid];
        if (STATS) { scs[tid] = 0.f; scq[tid] = 0.f; }
    }
    // stage A tile with input transform
    {
        float4* Asv = (float4*)Asm;
#pragma unroll
        for (int i = 0; i < 8; i++) {
            int idx = tid + i * 256;
            int r = idx >> 5;
            int c4 = idx & 31;
            int gr = row0 + r;
            float4 v = make_float4(0.f, 0.f, 0.f, 0.f);
            if (gr < M) {
                v = ((const float4*)A0)[(size_t)gr * 32 + c4];
                if (IN_MODE == 1) {
                    float4 u = ((const float4*)A1)[(size_t)gr * 32 + c4];
                    v.x += u.x; v.y += u.y; v.z += u.z; v.w += u.w;
                } else if (IN_MODE == 2) {
                    int col = c4 * 4;
                    v.x = fmaxf(v.x * sscale[col + 0] + sshift[col + 0], 0.f);
                    v.y = fmaxf(v.y * sscale[col + 1] + sshift[col + 1], 0.f);
                    v.z = fmaxf(v.z * sscale[col + 2] + sshift[col + 2], 0.f);
                    v.w = fmaxf(v.w * sscale[col + 3] + sshift[col + 3], 0.f);
                }
            }
            Asv[idx] = v;
        }
    }
    __syncthreads();

    int rid = tid >> 5;  // warp -> rows rid*8..+7
    int cid = tid & 31;  // lane -> cols cid + {0,32,64,96}
    unsigned long long acc[8][4];
#pragma unroll
    for (int i = 0; i < 8; i++)
#pragma unroll
        for (int c = 0; c < 4; c++) acc[i][c] = 0ull;

    const float4* Asv = (const float4*)Asm;
#pragma unroll
    for (int k4 = 0; k4 < 32; k4++) {
        unsigned long long a2[8][2];
#pragma unroll
        for (int i = 0; i < 8; i++) {
            float4 av = Asv[(rid * 8 + i) * 32 + k4];  // warp-broadcast
            a2[i][0] = *(unsigned long long*)&av.x;
            a2[i][1] = *(unsigned long long*)&av.z;
        }
#pragma unroll
        for (int c = 0; c < 4; c++) {
            float4 wv = *(const float4*)(Wt + (cid + 32 * c) * WT_STRIDE + k4 * 4);
            unsigned long long w0 = *(unsigned long long*)&wv.x;
            unsigned long long w1 = *(unsigned long long*)&wv.z;
#pragma unroll
            for (int i = 0; i < 8; i++) {
                ffma2(acc[i][c], a2[i][0], w0);
                ffma2(acc[i][c], a2[i][1], w1);
            }
        }
    }

    // epilogue
    float cs[4] = {0.f, 0.f, 0.f, 0.f};
    float cq[4] = {0.f, 0.f, 0.f, 0.f};
#pragma unroll
    for (int i = 0; i < 8; i++) {
        int gr = row0 + rid * 8 + i;
        if (gr < M) {
#pragma unroll
            for (int c = 0; c < 4; c++) {
                int col = cid + 32 * c;
                float2 p = unpack2(acc[i][c]);
                float y = p.x + p.y + sbias[col];
                if (STATS) { cs[c] += y; cq[c] += y * y; }
                C[(size_t)gr * 128 + col] = OUT_RELU ? fmaxf(y, 0.f) : y;
            }
            if (ZEROA)
                ((float4*)aggz)[(size_t)gr * 32 + cid] = make_float4(0.f, 0.f, 0.f, 0.f);
        }
    }
    if (STATS) {
#pragma unroll
        for (int c = 0; c < 4; c++) {
            atomicAdd(&scs[cid + 32 * c], cs[c]);
            atomicAdd(&scq[cid + 32 * c], cq[c]);
        }
        __syncthreads();
        if (tid < 128) {
            atomicAdd(&colsum[tid], scs[tid]);
            atomicAdd(&colsumsq[tid], scq[tid]);
        }
    }
}

// ---------------- code MLP branch ----------------
__global__ void code_mlp(const float* __restrict__ code_x,
                         const float* __restrict__ w1, const float* __restrict__ b1,
                         const float* __restrict__ w2, const float* __restrict__ b2,
                         const float* __restrict__ w3, const float* __restrict__ b3,
                         float* __restrict__ code_out) {
    __shared__ float buf0[128], buf1[128];
    __shared__ float red[64];
    __shared__ float s_mx, s_lse;
    int g = blockIdx.x, j = threadIdx.x;
    buf0[j] = code_x[(size_t)g * 128 + j];
    __syncthreads();
    float acc = b1[j];
    for (int k = 0; k < 128; k++) acc += buf0[k] * w1[k * 128 + j];
    buf1[j] = fmaxf(acc, 0.f);
    __syncthreads();
    float acc2 = b2[j];
    for (int k = 0; k < 128; k++) acc2 += buf1[k] * w2[k * 128 + j];
    buf0[j] = fmaxf(acc2, 0.f);
    __syncthreads();
    float v = 0.f;
    if (j < 64) {
        v = b3[j];
        for (int k = 0; k < 128; k++) v += buf0[k] * w3[k * 64 + j];
        red[j] = v;
    }
    __syncthreads();
    if (j == 0) {
        float m = red[0];
        for (int i = 1; i < 64; i++) m = fmaxf(m, red[i]);
        float s = 0.f;
        for (int i = 0; i < 64; i++) s += expf(red[i] - m);
        s_mx = m;
        s_lse = logf(s);
    }
    __syncthreads();
    if (j < 64) code_out[(size_t)g * 64 + j] = v - s_mx - s_lse;
}

// ---------------- head ----------------
__global__ void head_kernel(const float* __restrict__ pool,
                            const float* __restrict__ l1w, const float* __restrict__ l1b,
                            const float* __restrict__ l2w, const float* __restrict__ l2b,
                            const float* __restrict__ code,
                            const float* __restrict__ finw, const float* __restrict__ finb,
                            float* __restrict__ out) {
    __shared__ float p[128], t[128], cc[128];
    __shared__ float r0[128], r1[128];
    int g = blockIdx.x, j = threadIdx.x;
    p[j] = pool[(size_t)g * 128 + j];
    __syncthreads();
    float a = l1b[j];
    for (int k = 0; k < 128; k++) a += p[k] * l1w[k * 128 + j];
    t[j] = fmaxf(a, 0.f);
    __syncthreads();
    if (j < 64) {
        float v = l2b[j];
        for (int k = 0; k < 128; k++) v += t[k] * l2w[k * 64 + j];
        cc[64 + j] = v;
        cc[j] = code[(size_t)g * 64 + j];
    }
    __syncthreads();
    r0[j] = cc[j] * finw[j * 2 + 0];
    r1[j] = cc[j] * finw[j * 2 + 1];
    __syncthreads();
    if (j == 0) {
        float o0 = finb[0], o1 = finb[1];
        for (int k = 0; k < 128; k++) { o0 += r0[k]; o1 += r1[k]; }
        float m = fmaxf(o0, o1);
        float l = m + logf(expf(o0 - m) + expf(o1 - m));
        out[(size_t)g * 2 + 0] = o0 - l;
        out[(size_t)g * 2 + 1] = o1 - l;
    }
}

// ---------------- launcher ----------------
extern "C" void kernel_launch(void* const* d_in, const int* in_sizes, int n_in,
                              void* d_out, int out_size) {
    const float* x = (const float*)d_in[0];
    const int* ei_raw = (const int*)d_in[1];
    const int* batch_raw = (const int*)d_in[2];
    const float* code_x = (const float*)d_in[3];
    const float* c1_w1 = (const float*)d_in[4];
    const float* c1_b1 = (const float*)d_in[5];
    const float* c1_g = (const float*)d_in[6];
    const float* c1_be = (const float*)d_in[7];
    const float* c1_w2 = (const float*)d_in[8];
    const float* c1_b2 = (const float*)d_in[9];
    const float* c2_w1 = (const float*)d_in[10];
    const float* c2_b1 = (const float*)d_in[11];
    const float* c2_g = (const float*)d_in[12];
    const float* c2_be = (const float*)d_in[13];
    const float* c2_w2 = (const float*)d_in[14];
    const float* c2_b2 = (const float*)d_in[15];
    const float* gl1_w = (const float*)d_in[16];
    const float* gl1_b = (const float*)d_in[17];
    const float* gl2_w = (const float*)d_in[18];
    const float* gl2_b = (const float*)d_in[19];
    const float* fc1_w = (const float*)d_in[20];
    const float* fc1_b = (const float*)d_in[21];
    const float* fc2_w = (const float*)d_in[22];
    const float* fc2_b = (const float*)d_in[23];
    const float* fc3_w = (const float*)d_in[24];
    const float* fc3_b = (const float*)d_in[25];
    const float* fin_w = (const float*)d_in[26];
    const float* fin_b = (const float*)d_in[27];
    float* out = (float*)d_out;

    float *agg, *y, *h, *pool, *code, *cs1, *cq1, *cs2, *cq2;
    int *srcp, *dstp, *batchp;
    cudaGetSymbolAddress((void**)&agg, g_agg);
    cudaGetSymbolAddress((void**)&y, g_y);
    cudaGetSymbolAddress((void**)&h, g_h);
    cudaGetSymbolAddress((void**)&pool, g_pool);
    cudaGetSymbolAddress((void**)&code, g_code);
    cudaGetSymbolAddress((void**)&cs1, g_colsum1);
    cudaGetSymbolAddress((void**)&cq1, g_colsumsq1);
    cudaGetSymbolAddress((void**)&cs2, g_colsum2);
    cudaGetSymbolAddress((void**)&cq2, g_colsumsq2);
    cudaGetSymbolAddress((void**)&srcp, g_src);
    cudaGetSymbolAddress((void**)&dstp, g_dst);
    cudaGetSymbolAddress((void**)&batchp, g_batch);

    cudaFuncSetAttribute(gemm128<1, false, true, false>, cudaFuncAttributeMaxDynamicSharedMemorySize, GEMM_SMEM);
    cudaFuncSetAttribute(gemm128<2, true, false, true>, cudaFuncAttributeMaxDynamicSharedMemorySize, GEMM_SMEM);
    cudaFuncSetAttribute(gemm128<2, true, false, false>, cudaFuncAttributeMaxDynamicSharedMemorySize, GEMM_SMEM);

    const int gemm_blocks = (NN + 63) / 64;           // 1563
    const int edge_blocks = (EE * 32 + 255) / 256;    // 62500

    convert_edges_zero<<<2048, 256>>>(ei_raw, srcp, dstp, agg);                        // 0
    edge_agg<<<edge_blocks, 256>>>(x, srcp, dstp, agg, EE);                            // 1
    convert_batch<<<256, 256>>>(batch_raw, batchp, pool, cs1, cq1, cs2, cq2);          // 2

    // ---- conv1 ----
    gemm128<1, false, true, false><<<gemm_blocks, 256, GEMM_SMEM>>>(                   // 3 (profiled)
        x, agg, nullptr, nullptr, nullptr, nullptr, c1_w1, c1_b1, y, NN, cs1, cq1, nullptr);
    code_mlp<<<GG, 128>>>(code_x, fc1_w, fc1_b, fc2_w, fc2_b, fc3_w, fc3_b, code);     // 4
    // gemm2: fused BN-finalize(cs1) + relu; epilogue zeroes agg for conv2
    gemm128<2, true, false, true><<<gemm_blocks, 256, GEMM_SMEM>>>(
        y, nullptr, cs1, cq1, c1_g, c1_be, c1_w2, c1_b2, h, NN, nullptr, nullptr, agg);

    // ---- conv2 ----
    edge_agg<<<edge_blocks, 256>>>(h, srcp, dstp, agg, EE);
    gemm128<1, false, true, false><<<gemm_blocks, 256, GEMM_SMEM>>>(
        h, agg, nullptr, nullptr, nullptr, nullptr, c2_w1, c2_b1, y, NN, cs2, cq2, nullptr);
    gemm128<2, true, false, false><<<gemm_blocks, 256, GEMM_SMEM>>>(
        y, nullptr, cs2, cq2, c2_g, c2_be, c2_w2, c2_b2, h, NN, nullptr, nullptr, nullptr);

    // ---- pool + head ----
    pool_kernel<<<(NN * 32 + 255) / 256, 256>>>(h, batchp, pool, NN);
    head_kernel<<<GG, 128>>>(pool, gl1_w, gl1_b, gl2_w, gl2_b, code, fin_w, fin_b, out);
}